// round 1
// baseline (speedup 1.0000x reference)
#include <cuda_runtime.h>

// ---------------------------------------------------------------------------
// NLIF recurrent spiking net, persistent-kernel implementation.
//
// T=2048 steps. Per step: I_tot = s @ W_syn_m + s_fast @ W_fast + x_t @ W_in + I_o
// Weights are SMEM-resident (column slices per CTA), state vectors s / s_fast
// double-buffered in global (L2), custom grid barrier per step.
// ---------------------------------------------------------------------------

#define NN 2048
#define TT 2048
#define G  147           // number of CTAs (<= SM count 148, 1 CTA/SM)
#define CPT 14           // columns per CTA (147*14 = 2058 >= 2048)
#define NTHREADS 256
#define NWARPS 8
#define COLSTRIDE 2052   // padded column stride in floats (16B-aligned per column)

// dynamic smem: 2 weight slabs + reduction scratch
#define SMEM_BYTES ((2 * CPT * COLSTRIDE + CPT * NWARPS) * 4)

// persistent device state (no allocations allowed)
__device__ __align__(16) float g_s[2][NN];
__device__ __align__(16) float g_sf[2][NN];
__device__ float g_part[TT * G * 2];
__device__ unsigned g_count = 0;
__device__ unsigned g_gen = 0;

__device__ __forceinline__ float4 ldcg4(const float* p) {
    return __ldcg(reinterpret_cast<const float4*>(p));
}

__device__ __forceinline__ void grid_barrier() {
    __syncthreads();
    if (threadIdx.x == 0) {
        unsigned my = *((volatile unsigned*)&g_gen);
        if (atomicAdd(&g_count, 1u) == (unsigned)(G - 1)) {
            *((volatile unsigned*)&g_count) = 0u;
            __threadfence();
            atomicAdd(&g_gen, 1u);
        } else {
            while (*((volatile unsigned*)&g_gen) == my) { }
        }
        __threadfence();
    }
    __syncthreads();
}

__global__ void __launch_bounds__(NTHREADS, 1)
nlif_kernel(const float* __restrict__ x_in,    // [T][2]
            const float* __restrict__ W_syn,   // [N][N]
            const float* __restrict__ W_fast,  // [N][N]
            const float* __restrict__ W_in,    // [2][N]
            const float* __restrict__ I_o,     // [N]
            const float* __restrict__ O,       // [2][N]
            float* __restrict__ out_spikes,    // [T][N]
            float* __restrict__ out_vs)        // [T][N]
{
    extern __shared__ float smem[];
    float* Ws  = smem;                           // [CPT][COLSTRIDE]
    float* Wf  = smem + CPT * COLSTRIDE;         // [CPT][COLSTRIDE]
    float* red = smem + 2 * CPT * COLSTRIDE;     // [CPT][NWARPS]

    const int tid  = threadIdx.x;
    const int warp = tid >> 5;
    const int lane = tid & 31;
    const int b    = blockIdx.x;
    const int j0   = b * CPT;

    // ---- prologue: stage this CTA's weight columns into SMEM (column-major) ----
    for (int i = warp; i < NN; i += NWARPS) {
        if (lane < CPT) {
            int j = j0 + lane;
            float ws = 0.f, wf = 0.f;
            if (j < NN) {
                ws = W_syn[(size_t)i * NN + j];
                wf = W_fast[(size_t)i * NN + j];
                if (i == j) ws = 0.f;            // zero the diagonal (self-recurrence mask)
            }
            Ws[lane * COLSTRIDE + i] = ws;
            Wf[lane * COLSTRIDE + i] = wf;
        }
    }

    // per-column persistent state lives in warp-0 registers
    float v = 0.f, s = 0.f;
    float wi0 = 0.f, wi1 = 0.f, io = 0.f, o0 = 0.f, o1 = 0.f;
    const int j = j0 + lane;
    const bool active = (warp == 0) && (lane < CPT) && (j < NN);
    if (active) {
        wi0 = W_in[j];
        wi1 = W_in[NN + j];
        io  = I_o[j];
        o0  = O[j];
        o1  = O[NN + j];
        __stcg(&g_s[0][j], 0.f);     // t=0 reads parity-0 buffers
        __stcg(&g_sf[0][j], 0.f);
    }
    __threadfence();
    grid_barrier();

    const int i0 = tid * 8;          // each thread owns 8 contiguous rows

    for (int t = 0; t < TT; t++) {
        const int rb = t & 1;
        const int wb = rb ^ 1;
        const float* sr = g_s[rb];
        const float* fr = g_sf[rb];

        // bypass L1 (other CTAs wrote these last step)
        const float4 sa = ldcg4(sr + i0);
        const float4 sb = ldcg4(sr + i0 + 4);
        const float4 fa = ldcg4(fr + i0);
        const float4 fb = ldcg4(fr + i0 + 4);

        float acc[CPT];
        #pragma unroll
        for (int c = 0; c < CPT; c++) {
            const float4 w0 = *reinterpret_cast<const float4*>(&Ws[c * COLSTRIDE + i0]);
            const float4 w1 = *reinterpret_cast<const float4*>(&Ws[c * COLSTRIDE + i0 + 4]);
            const float4 f0 = *reinterpret_cast<const float4*>(&Wf[c * COLSTRIDE + i0]);
            const float4 f1 = *reinterpret_cast<const float4*>(&Wf[c * COLSTRIDE + i0 + 4]);
            float a = 0.f;
            a = fmaf(sa.x, w0.x, a); a = fmaf(sa.y, w0.y, a);
            a = fmaf(sa.z, w0.z, a); a = fmaf(sa.w, w0.w, a);
            a = fmaf(sb.x, w1.x, a); a = fmaf(sb.y, w1.y, a);
            a = fmaf(sb.z, w1.z, a); a = fmaf(sb.w, w1.w, a);
            a = fmaf(fa.x, f0.x, a); a = fmaf(fa.y, f0.y, a);
            a = fmaf(fa.z, f0.z, a); a = fmaf(fa.w, f0.w, a);
            a = fmaf(fb.x, f1.x, a); a = fmaf(fb.y, f1.y, a);
            a = fmaf(fb.z, f1.z, a); a = fmaf(fb.w, f1.w, a);
            acc[c] = a;
        }

        // intra-warp tree reduce, then stash per-warp partials
        #pragma unroll
        for (int c = 0; c < CPT; c++) {
            float x = acc[c];
            x += __shfl_down_sync(0xffffffffu, x, 16);
            x += __shfl_down_sync(0xffffffffu, x, 8);
            x += __shfl_down_sync(0xffffffffu, x, 4);
            x += __shfl_down_sync(0xffffffffu, x, 2);
            x += __shfl_down_sync(0xffffffffu, x, 1);
            if (lane == 0) red[c * NWARPS + warp] = x;
        }
        __syncthreads();

        if (warp == 0) {
            float r0 = 0.f, r1 = 0.f;
            if (active) {
                const float4 p0 = *reinterpret_cast<const float4*>(&red[lane * NWARPS]);
                const float4 p1 = *reinterpret_cast<const float4*>(&red[lane * NWARPS + 4]);
                const float sum = ((p0.x + p0.y) + (p0.z + p0.w)) +
                                  ((p1.x + p1.y) + (p1.z + p1.w));
                const float x0 = x_in[2 * t];
                const float x1 = x_in[2 * t + 1];

                const float I_tot  = sum + x0 * wi0 + x1 * wi1 + io;
                const float dv     = (I_tot - v) / 10.0f;          // TAU_M
                const float v_next = v + dv;
                const float gating = fminf(fmaxf(v_next, -1.f), 1.f);
                const float dvc    = fminf(fmaxf(dv, -1.f), 1.f);
                const float gd     = gating * dvc;
                const float s_new  = s + (gd - s) / 10.0f;         // TAU_S
                const float sp     = (v_next >=  1.f) ? 1.f : 0.f;
                const float sn     = (v_next <= -1.f) ? 1.f : 0.f;
                // not_spiked = 1 - (sp-1)/(-1) + (sn-1)/(-1) = 1 + sp - sn (replicated exactly)
                const float v_new  = (1.f + sp - sn) * v_next;

                v = v_new; s = s_new;

                __stcg(&g_s[wb][j], s_new);
                __stcg(&g_sf[wb][j], gd);
                out_spikes[(size_t)t * NN + j] = sp;
                out_vs[(size_t)t * NN + j]     = v_new;

                r0 = o0 * s_new;
                r1 = o1 * s_new;
            }
            // readout partial for this CTA (inactive lanes contribute 0)
            #pragma unroll
            for (int o = 16; o; o >>= 1) {
                r0 += __shfl_down_sync(0xffffffffu, r0, o);
                r1 += __shfl_down_sync(0xffffffffu, r1, o);
            }
            if (lane == 0) {
                g_part[((size_t)t * G + b) * 2 + 0] = r0;
                g_part[((size_t)t * G + b) * 2 + 1] = r1;
            }
            __threadfence();
        }
        grid_barrier();
    }
}

// epilogue: readouts[t] = sum over CTAs of per-CTA partial (O @ s_new)
__global__ void readout_kernel(float* __restrict__ out_ro) {
    const int t = blockIdx.x * blockDim.x + threadIdx.x;
    if (t < TT) {
        float a = 0.f, c = 0.f;
        const float* p = &g_part[(size_t)t * G * 2];
        #pragma unroll 7
        for (int bb = 0; bb < G; bb++) {
            a += p[2 * bb];
            c += p[2 * bb + 1];
        }
        out_ro[2 * t]     = a;
        out_ro[2 * t + 1] = c;
    }
}

extern "C" void kernel_launch(void* const* d_in, const int* in_sizes, int n_in,
                              void* d_out, int out_size) {
    const float* x_in   = (const float*)d_in[0];
    const float* W_syn  = (const float*)d_in[1];
    const float* W_fast = (const float*)d_in[2];
    const float* W_in   = (const float*)d_in[3];
    const float* I_o    = (const float*)d_in[4];
    const float* O      = (const float*)d_in[5];

    float* out        = (float*)d_out;
    float* out_spikes = out;                                // [T][N]
    float* out_ro     = out + (size_t)TT * NN;              // [T][2]
    float* out_vs     = out + (size_t)TT * NN + 2 * TT;     // [T][N]

    cudaFuncSetAttribute(nlif_kernel,
                         cudaFuncAttributeMaxDynamicSharedMemorySize, SMEM_BYTES);

    nlif_kernel<<<G, NTHREADS, SMEM_BYTES>>>(x_in, W_syn, W_fast, W_in, I_o, O,
                                             out_spikes, out_vs);
    readout_kernel<<<(TT + 127) / 128, 128>>>(out_ro);
}

// round 3
// speedup vs baseline: 1.5283x; 1.5283x over previous
#include <cuda_runtime.h>

// ---------------------------------------------------------------------------
// NLIF recurrent spiking net — persistent kernel, SMEM-resident weights.
// Round 2 (resubmit after infra failure): conflict-free SMEM layout +
// flag-array sync (no central barrier, no MEMBAR.GPU), outputs off the
// critical path. Added nanosleep backoff in the poll loop.
// ---------------------------------------------------------------------------

#define NN 2048
#define TT 2048
#define G  147           // CTAs, 1 per SM (all co-resident on 148 SMs)
#define CPT 14           // columns per CTA (147*14 = 2058 >= 2048)
#define NTHREADS 256
#define NWARPS 8
#define CSTRF 4096       // floats per column slab: 2048 rows x (ws,wf)

#define SMEM_BYTES ((CPT * CSTRF + CPT * NWARPS) * 4)

// persistent device state (no allocations allowed)
__device__ __align__(16) float2 g_state[2][NN];   // (s, s_fast), double-buffered
__device__ unsigned g_flag[G];                    // monotonic per-CTA progress flags
__device__ float g_part[TT * G * 2];              // per-CTA readout partials

__device__ __forceinline__ unsigned ld_relaxed_u32(const unsigned* p) {
    unsigned v;
    asm volatile("ld.relaxed.gpu.global.u32 %0, [%1];" : "=r"(v) : "l"(p));
    return v;
}
__device__ __forceinline__ void red_release_add(unsigned* p, unsigned v) {
    asm volatile("red.release.gpu.global.add.u32 [%0], %1;" :: "l"(p), "r"(v) : "memory");
}
__device__ __forceinline__ void fence_acq() {
    asm volatile("fence.acq_rel.gpu;" ::: "memory");
}

__global__ void __launch_bounds__(NTHREADS, 1)
nlif_kernel(const float* __restrict__ x_in,    // [T][2]
            const float* __restrict__ W_syn,   // [N][N]
            const float* __restrict__ W_fast,  // [N][N]
            const float* __restrict__ W_in,    // [2][N]
            const float* __restrict__ I_o,     // [N]
            const float* __restrict__ O,       // [2][N]
            float* __restrict__ out_spikes,    // [T][N]
            float* __restrict__ out_vs)        // [T][N]
{
    extern __shared__ float smem[];
    float* Wc  = smem;                    // [CPT][CSTRF] : per pair p, (ws0,wf0,ws1,wf1)
    float* red = smem + CPT * CSTRF;      // [CPT][NWARPS]

    const int tid  = threadIdx.x;
    const int warp = tid >> 5;
    const int lane = tid & 31;
    const int b    = blockIdx.x;
    const int j0   = b * CPT;

    // ---- epoch base for monotonic flags (handles graph replays) ----
    const unsigned base = g_flag[b];   // single-writer (self, prior launch): race-free

    // ---- stage weight columns into SMEM, interleaved (ws,wf) per row ----
    for (int i = warp; i < NN; i += NWARPS) {
        if (lane < CPT) {
            const int jj = j0 + lane;
            float ws = 0.f, wf = 0.f;
            if (jj < NN) {
                ws = W_syn[(size_t)i * NN + jj];
                wf = W_fast[(size_t)i * NN + jj];
                if (i == jj) ws = 0.f;              // self-recurrence mask
            }
            const int p = i >> 1, r = i & 1;
            Wc[lane * CSTRF + p * 4 + r * 2 + 0] = ws;
            Wc[lane * CSTRF + p * 4 + r * 2 + 1] = wf;
        }
    }

    // ---- per-column persistent state in warp-0 registers ----
    const int j = j0 + lane;
    const bool active = (warp == 0) && (lane < CPT) && (j < NN);
    float v = 0.f, s = 0.f;
    float wi0 = 0.f, wi1 = 0.f, io = 0.f, o0 = 0.f, o1 = 0.f;
    if (active) {
        wi0 = W_in[j];
        wi1 = W_in[NN + j];
        io  = I_o[j];
        o0  = O[j];
        o1  = O[NN + j];
        __stcg(&g_state[0][j], make_float2(0.f, 0.f));   // t=0 reads parity-0 zeros
    }
    if (warp == 0 && lane < CPT) red_release_add(&g_flag[b], 1u);  // init "step"

    for (int t = 0; t < TT; t++) {
        const int rb = t & 1;
        const int wb = rb ^ 1;

        float x0 = 0.f, x1 = 0.f;
        if (warp == 0) {
            // prefetch external input before the wait
            x0 = __ldg(&x_in[2 * t]);
            x1 = __ldg(&x_in[2 * t + 1]);
            // wait until every CTA has published state for this step
            const unsigned tgt = base + 14u * (unsigned)(t + 1);
            bool ok;
            bool first = true;
            do {
                if (!first) __nanosleep(64);
                first = false;
                ok = true;
                #pragma unroll
                for (int k = 0; k < 5; k++) {
                    const int idx = lane + 32 * k;
                    if (idx < G) {
                        const unsigned f = ld_relaxed_u32(&g_flag[idx]);
                        ok &= ((int)(f - tgt) >= 0);
                    }
                }
            } while (!__all_sync(0xffffffffu, ok));
            fence_acq();
        }
        __syncthreads();   // also orders SMEM staging on the first iteration

        // ---- load state: 4 coalesced float4 (rows 2p, 2p+1 per float4) ----
        const float2* srow = g_state[rb];
        float4 st[4];
        #pragma unroll
        for (int k = 0; k < 4; k++) {
            const int p = k * NTHREADS + tid;
            st[k] = __ldcg(reinterpret_cast<const float4*>(&srow[2 * p]));
        }

        // ---- dot products: conflict-free LDS.128 (consecutive lanes -> consecutive 16B) ----
        float acc[CPT];
        #pragma unroll
        for (int c = 0; c < CPT; c++) {
            float a = 0.f;
            #pragma unroll
            for (int k = 0; k < 4; k++) {
                const int p = k * NTHREADS + tid;
                const float4 w = *reinterpret_cast<const float4*>(&Wc[c * CSTRF + p * 4]);
                a = fmaf(st[k].x, w.x, a);   // s[2p]   * ws
                a = fmaf(st[k].y, w.y, a);   // sf[2p]  * wf
                a = fmaf(st[k].z, w.z, a);   // s[2p+1] * ws
                a = fmaf(st[k].w, w.w, a);   // sf[2p+1]* wf
            }
            acc[c] = a;
        }

        // ---- intra-warp tree reduce, stash per-warp partials ----
        #pragma unroll
        for (int c = 0; c < CPT; c++) {
            float x = acc[c];
            x += __shfl_down_sync(0xffffffffu, x, 16);
            x += __shfl_down_sync(0xffffffffu, x, 8);
            x += __shfl_down_sync(0xffffffffu, x, 4);
            x += __shfl_down_sync(0xffffffffu, x, 2);
            x += __shfl_down_sync(0xffffffffu, x, 1);
            if (lane == 0) red[c * NWARPS + warp] = x;
        }
        __syncthreads();

        if (warp == 0) {
            float r0 = 0.f, r1 = 0.f;
            float s_new = 0.f, gd = 0.f, spk = 0.f, v_new = 0.f;
            if (active) {
                const float4 p0 = *reinterpret_cast<const float4*>(&red[lane * NWARPS]);
                const float4 p1 = *reinterpret_cast<const float4*>(&red[lane * NWARPS + 4]);
                const float sum = ((p0.x + p0.y) + (p0.z + p0.w)) +
                                  ((p1.x + p1.y) + (p1.z + p1.w));

                const float I_tot  = sum + x0 * wi0 + x1 * wi1 + io;
                const float dv     = (I_tot - v) / 10.0f;          // TAU_M
                const float v_next = v + dv;
                const float gating = fminf(fmaxf(v_next, -1.f), 1.f);
                const float dvc    = fminf(fmaxf(dv, -1.f), 1.f);
                gd                 = gating * dvc;
                s_new              = s + (gd - s) / 10.0f;         // TAU_S
                spk                = (v_next >=  1.f) ? 1.f : 0.f;
                const float sn     = (v_next <= -1.f) ? 1.f : 0.f;
                v_new              = (1.f + spk - sn) * v_next;    // matches reference exactly

                v = v_new; s = s_new;
                __stcg(&g_state[wb][j], make_float2(s_new, gd));
            }
            // publish progress FIRST (release orders each lane's own state store)
            if (lane < CPT) red_release_add(&g_flag[b], 1u);

            // non-critical outputs after the release
            if (active) {
                out_spikes[(size_t)t * NN + j] = spk;
                out_vs[(size_t)t * NN + j]     = v_new;
                r0 = o0 * s_new;
                r1 = o1 * s_new;
            }
            #pragma unroll
            for (int o = 16; o; o >>= 1) {
                r0 += __shfl_down_sync(0xffffffffu, r0, o);
                r1 += __shfl_down_sync(0xffffffffu, r1, o);
            }
            if (lane == 0) {
                g_part[((size_t)t * G + b) * 2 + 0] = r0;
                g_part[((size_t)t * G + b) * 2 + 1] = r1;
            }
        }
    }
}

// epilogue: readouts[t] = sum over CTAs of per-CTA partial (O @ s_new)
__global__ void readout_kernel(float* __restrict__ out_ro) {
    const int t = blockIdx.x * blockDim.x + threadIdx.x;
    if (t < TT) {
        float a = 0.f, c = 0.f;
        const float* p = &g_part[(size_t)t * G * 2];
        #pragma unroll 7
        for (int bb = 0; bb < G; bb++) {
            a += p[2 * bb];
            c += p[2 * bb + 1];
        }
        out_ro[2 * t]     = a;
        out_ro[2 * t + 1] = c;
    }
}

extern "C" void kernel_launch(void* const* d_in, const int* in_sizes, int n_in,
                              void* d_out, int out_size) {
    const float* x_in   = (const float*)d_in[0];
    const float* W_syn  = (const float*)d_in[1];
    const float* W_fast = (const float*)d_in[2];
    const float* W_in   = (const float*)d_in[3];
    const float* I_o    = (const float*)d_in[4];
    const float* O      = (const float*)d_in[5];

    float* out        = (float*)d_out;
    float* out_spikes = out;                                // [T][N]
    float* out_ro     = out + (size_t)TT * NN;              // [T][2]
    float* out_vs     = out + (size_t)TT * NN + 2 * TT;     // [T][N]

    cudaFuncSetAttribute(nlif_kernel,
                         cudaFuncAttributeMaxDynamicSharedMemorySize, SMEM_BYTES);

    nlif_kernel<<<G, NTHREADS, SMEM_BYTES>>>(x_in, W_syn, W_fast, W_in, I_o, O,
                                             out_spikes, out_vs);
    readout_kernel<<<(TT + 127) / 128, 128>>>(out_ro);
}

// round 5
// speedup vs baseline: 1.8773x; 1.2284x over previous
#include <cuda_runtime.h>

// ---------------------------------------------------------------------------
// NLIF recurrent spiking net — persistent kernel.
// Round 3 resubmit (infra flake): half the weights register-resident (LDS
// crossbar was the compute bottleneck), single per-step release counter
// instead of 147-flag scan.
// ---------------------------------------------------------------------------

#define NN 2048
#define TT 2048
#define G  147           // CTAs, 1 per SM (all co-resident on 148 SMs)
#define CPT 14           // columns per CTA (147*14 = 2058 >= 2048)
#define NTHREADS 256
#define NWARPS 8
#define CSTRF 4096       // floats per column slab: 2048 rows x (ws,wf)

#define SMEM_BYTES ((CPT * CSTRF + CPT * NWARPS) * 4)

// persistent device state (no allocations allowed)
__device__ __align__(16) float2 g_state[2][NN];   // (s, s_fast), double-buffered
__device__ unsigned g_cnt[TT + 2];                // per-step counters + epoch slot
__device__ float g_part[TT * G * 2];              // per-CTA readout partials

__device__ __forceinline__ unsigned ld_relaxed_u32(const unsigned* p) {
    unsigned v;
    asm volatile("ld.relaxed.gpu.global.u32 %0, [%1];" : "=r"(v) : "l"(p));
    return v;
}
__device__ __forceinline__ void red_release_add(unsigned* p, unsigned v) {
    asm volatile("red.release.gpu.global.add.u32 [%0], %1;" :: "l"(p), "r"(v) : "memory");
}
__device__ __forceinline__ void fence_acq() {
    asm volatile("fence.acq_rel.gpu;" ::: "memory");
}

__global__ void __launch_bounds__(NTHREADS, 1)
nlif_kernel(const float* __restrict__ x_in,    // [T][2]
            const float* __restrict__ W_syn,   // [N][N]
            const float* __restrict__ W_fast,  // [N][N]
            const float* __restrict__ W_in,    // [2][N]
            const float* __restrict__ I_o,     // [N]
            const float* __restrict__ O,       // [2][N]
            float* __restrict__ out_spikes,    // [T][N]
            float* __restrict__ out_vs)        // [T][N]
{
    extern __shared__ float smem[];
    float* Wc  = smem;                    // [CPT][CSTRF] : per pair p, (ws0,wf0,ws1,wf1)
    float* red = smem + CPT * CSTRF;      // [CPT][NWARPS]

    const int tid  = threadIdx.x;
    const int warp = tid >> 5;
    const int lane = tid & 31;
    const int b    = blockIdx.x;
    const int j0   = b * CPT;

    // epoch base: all counters equal R*G at launch start; slot TT+1 is bumped
    // once per CTA at kernel end, so it reads exactly R*G here.
    const unsigned base = ld_relaxed_u32(&g_cnt[TT + 1]);
    const unsigned tgt0 = base + (unsigned)G;

    // ---- stage weight columns into SMEM, interleaved (ws,wf) per row ----
    for (int i = warp; i < NN; i += NWARPS) {
        if (lane < CPT) {
            const int jj = j0 + lane;
            float ws = 0.f, wf = 0.f;
            if (jj < NN) {
                ws = W_syn[(size_t)i * NN + jj];
                wf = W_fast[(size_t)i * NN + jj];
                if (i == jj) ws = 0.f;              // self-recurrence mask
            }
            const int p = i >> 1, r = i & 1;
            Wc[lane * CSTRF + p * 4 + r * 2 + 0] = ws;
            Wc[lane * CSTRF + p * 4 + r * 2 + 1] = wf;
        }
    }
    __syncthreads();

    // ---- pull k=2,3 weight chunks into registers (112 regs/thread) ----
    float4 wr[CPT][2];
    #pragma unroll
    for (int c = 0; c < CPT; c++) {
        #pragma unroll
        for (int kk = 0; kk < 2; kk++) {
            const int p = (kk + 2) * NTHREADS + tid;
            wr[c][kk] = *reinterpret_cast<const float4*>(&Wc[c * CSTRF + p * 4]);
        }
    }

    // ---- per-column persistent state in warp-0 registers ----
    const int j = j0 + lane;
    const bool active = (warp == 0) && (lane < CPT) && (j < NN);
    float v = 0.f, s = 0.f;
    float wi0 = 0.f, wi1 = 0.f, io = 0.f, o0 = 0.f, o1 = 0.f;
    if (active) {
        wi0 = W_in[j];
        wi1 = W_in[NN + j];
        io  = I_o[j];
        o0  = O[j];
        o1  = O[NN + j];
        __stcg(&g_state[0][j], make_float2(0.f, 0.f));   // t=0 reads parity-0 zeros
    }
    if (warp == 0 && lane == 0) red_release_add(&g_cnt[0], 1u);  // initial publish

    for (int t = 0; t < TT; t++) {
        const int rb = t & 1;
        const int wb = rb ^ 1;

        float x0 = 0.f, x1 = 0.f;
        if (warp == 0) {
            x0 = __ldg(&x_in[2 * t]);            // prefetch input before the wait
            x1 = __ldg(&x_in[2 * t + 1]);
            // wait until all CTAs published state readable at step t
            const unsigned* cp = &g_cnt[t];
            unsigned f = ld_relaxed_u32(cp);
            while ((int)(f - tgt0) < 0) {
                __nanosleep(32);
                f = ld_relaxed_u32(cp);
            }
            fence_acq();
        }
        __syncthreads();

        // ---- load state: 4 coalesced float4 (rows 2p, 2p+1 per float4) ----
        const float2* srow = g_state[rb];
        float4 st[4];
        #pragma unroll
        for (int k = 0; k < 4; k++) {
            const int p = k * NTHREADS + tid;
            st[k] = __ldcg(reinterpret_cast<const float4*>(&srow[2 * p]));
        }

        // ---- dot products: k=0,1 from SMEM (conflict-free LDS.128), k=2,3 from regs ----
        float acc[CPT];
        #pragma unroll
        for (int c = 0; c < CPT; c++) {
            float a = 0.f;
            #pragma unroll
            for (int k = 0; k < 2; k++) {
                const int p = k * NTHREADS + tid;
                const float4 w = *reinterpret_cast<const float4*>(&Wc[c * CSTRF + p * 4]);
                a = fmaf(st[k].x, w.x, a);
                a = fmaf(st[k].y, w.y, a);
                a = fmaf(st[k].z, w.z, a);
                a = fmaf(st[k].w, w.w, a);
            }
            #pragma unroll
            for (int kk = 0; kk < 2; kk++) {
                const float4 w = wr[c][kk];
                const float4 sv = st[kk + 2];
                a = fmaf(sv.x, w.x, a);
                a = fmaf(sv.y, w.y, a);
                a = fmaf(sv.z, w.z, a);
                a = fmaf(sv.w, w.w, a);
            }
            acc[c] = a;
        }

        // ---- intra-warp tree reduce, stash per-warp partials ----
        #pragma unroll
        for (int c = 0; c < CPT; c++) {
            float x = acc[c];
            x += __shfl_down_sync(0xffffffffu, x, 16);
            x += __shfl_down_sync(0xffffffffu, x, 8);
            x += __shfl_down_sync(0xffffffffu, x, 4);
            x += __shfl_down_sync(0xffffffffu, x, 2);
            x += __shfl_down_sync(0xffffffffu, x, 1);
            if (lane == 0) red[c * NWARPS + warp] = x;
        }
        __syncthreads();

        if (warp == 0) {
            float r0 = 0.f, r1 = 0.f;
            float s_new = 0.f, gd = 0.f, spk = 0.f, v_new = 0.f;
            if (active) {
                const float4 p0 = *reinterpret_cast<const float4*>(&red[lane * NWARPS]);
                const float4 p1 = *reinterpret_cast<const float4*>(&red[lane * NWARPS + 4]);
                const float sum = ((p0.x + p0.y) + (p0.z + p0.w)) +
                                  ((p1.x + p1.y) + (p1.z + p1.w));

                const float I_tot  = sum + x0 * wi0 + x1 * wi1 + io;
                const float dv     = (I_tot - v) / 10.0f;          // TAU_M
                const float v_next = v + dv;
                const float gating = fminf(fmaxf(v_next, -1.f), 1.f);
                const float dvc    = fminf(fmaxf(dv, -1.f), 1.f);
                gd                 = gating * dvc;
                s_new              = s + (gd - s) / 10.0f;         // TAU_S
                spk                = (v_next >=  1.f) ? 1.f : 0.f;
                const float sn     = (v_next <= -1.f) ? 1.f : 0.f;
                v_new              = (1.f + spk - sn) * v_next;    // matches reference exactly

                v = v_new; s = s_new;
                __stcg(&g_state[wb][j], make_float2(s_new, gd));
            }
            // publish progress FIRST (release orders the state stores above)
            if (lane == 0) red_release_add(&g_cnt[t + 1], 1u);

            // non-critical outputs after the release
            if (active) {
                out_spikes[(size_t)t * NN + j] = spk;
                out_vs[(size_t)t * NN + j]     = v_new;
                r0 = o0 * s_new;
                r1 = o1 * s_new;
            }
            #pragma unroll
            for (int o = 16; o; o >>= 1) {
                r0 += __shfl_down_sync(0xffffffffu, r0, o);
                r1 += __shfl_down_sync(0xffffffffu, r1, o);
            }
            if (lane == 0) {
                g_part[((size_t)t * G + b) * 2 + 0] = r0;
                g_part[((size_t)t * G + b) * 2 + 1] = r1;
            }
        }
    }

    // bump the epoch slot (one per CTA per replay)
    if (warp == 0 && lane == 0) red_release_add(&g_cnt[TT + 1], 1u);
}

// epilogue: readouts[t] = sum over CTAs of per-CTA partial (O @ s_new)
__global__ void readout_kernel(float* __restrict__ out_ro) {
    const int t = blockIdx.x * blockDim.x + threadIdx.x;
    if (t < TT) {
        float a = 0.f, c = 0.f;
        const float* p = &g_part[(size_t)t * G * 2];
        #pragma unroll 7
        for (int bb = 0; bb < G; bb++) {
            a += p[2 * bb];
            c += p[2 * bb + 1];
        }
        out_ro[2 * t]     = a;
        out_ro[2 * t + 1] = c;
    }
}

extern "C" void kernel_launch(void* const* d_in, const int* in_sizes, int n_in,
                              void* d_out, int out_size) {
    const float* x_in   = (const float*)d_in[0];
    const float* W_syn  = (const float*)d_in[1];
    const float* W_fast = (const float*)d_in[2];
    const float* W_in   = (const float*)d_in[3];
    const float* I_o    = (const float*)d_in[4];
    const float* O      = (const float*)d_in[5];

    float* out        = (float*)d_out;
    float* out_spikes = out;                                // [T][N]
    float* out_ro     = out + (size_t)TT * NN;              // [T][2]
    float* out_vs     = out + (size_t)TT * NN + 2 * TT;     // [T][N]

    cudaFuncSetAttribute(nlif_kernel,
                         cudaFuncAttributeMaxDynamicSharedMemorySize, SMEM_BYTES);

    nlif_kernel<<<G, NTHREADS, SMEM_BYTES>>>(x_in, W_syn, W_fast, W_in, I_o, O,
                                             out_spikes, out_vs);
    readout_kernel<<<(TT + 127) / 128, 128>>>(out_ro);
}

// round 6
// speedup vs baseline: 2.2635x; 1.2057x over previous
#include <cuda_runtime.h>

// ---------------------------------------------------------------------------
// NLIF recurrent spiking net — persistent kernel.
// Round 5: 3 of 4 weight chunks register-resident (LDS fully hidden under
// FFMA floor), acquire-load sync (no MEMBAR.GPU), faster readout epilogue.
// ---------------------------------------------------------------------------

#define NN 2048
#define TT 2048
#define G  147           // CTAs, 1 per SM (all co-resident on 148 SMs)
#define CPT 14           // columns per CTA (147*14 = 2058 >= 2048)
#define NTHREADS 256
#define NWARPS 8
#define CSTRF 4096       // floats per column slab: 2048 rows x (ws,wf)

#define SMEM_BYTES ((CPT * CSTRF + CPT * NWARPS) * 4)

// persistent device state (no allocations allowed)
__device__ __align__(16) float2 g_state[2][NN];   // (s, s_fast), double-buffered
__device__ unsigned g_cnt[TT + 2];                // per-step counters + epoch slot
__device__ float g_part[TT * G * 2];              // per-CTA readout partials

__device__ __forceinline__ unsigned ld_relaxed_u32(const unsigned* p) {
    unsigned v;
    asm volatile("ld.relaxed.gpu.global.u32 %0, [%1];" : "=r"(v) : "l"(p));
    return v;
}
__device__ __forceinline__ unsigned ld_acquire_u32(const unsigned* p) {
    unsigned v;
    asm volatile("ld.acquire.gpu.global.u32 %0, [%1];" : "=r"(v) : "l"(p));
    return v;
}
__device__ __forceinline__ void red_release_add(unsigned* p, unsigned v) {
    asm volatile("red.release.gpu.global.add.u32 [%0], %1;" :: "l"(p), "r"(v) : "memory");
}

__global__ void __launch_bounds__(NTHREADS, 1)
nlif_kernel(const float* __restrict__ x_in,    // [T][2]
            const float* __restrict__ W_syn,   // [N][N]
            const float* __restrict__ W_fast,  // [N][N]
            const float* __restrict__ W_in,    // [2][N]
            const float* __restrict__ I_o,     // [N]
            const float* __restrict__ O,       // [2][N]
            float* __restrict__ out_spikes,    // [T][N]
            float* __restrict__ out_vs)        // [T][N]
{
    extern __shared__ float smem[];
    float* Wc  = smem;                    // [CPT][CSTRF] : per pair p, (ws0,wf0,ws1,wf1)
    float* red = smem + CPT * CSTRF;      // [CPT][NWARPS]

    const int tid  = threadIdx.x;
    const int warp = tid >> 5;
    const int lane = tid & 31;
    const int b    = blockIdx.x;
    const int j0   = b * CPT;

    // epoch base: all counters equal R*G at launch start; slot TT+1 is bumped
    // once per CTA at kernel end, so it reads exactly R*G here.
    const unsigned base = ld_relaxed_u32(&g_cnt[TT + 1]);
    const unsigned tgt0 = base + (unsigned)G;

    // ---- stage weight columns into SMEM, interleaved (ws,wf) per row ----
    for (int i = warp; i < NN; i += NWARPS) {
        if (lane < CPT) {
            const int jj = j0 + lane;
            float ws = 0.f, wf = 0.f;
            if (jj < NN) {
                ws = W_syn[(size_t)i * NN + jj];
                wf = W_fast[(size_t)i * NN + jj];
                if (i == jj) ws = 0.f;              // self-recurrence mask
            }
            const int p = i >> 1, r = i & 1;
            Wc[lane * CSTRF + p * 4 + r * 2 + 0] = ws;
            Wc[lane * CSTRF + p * 4 + r * 2 + 1] = wf;
        }
    }
    __syncthreads();

    // ---- pull k=1,2,3 weight chunks into registers (168 regs/thread) ----
    float4 wr[CPT][3];
    #pragma unroll
    for (int c = 0; c < CPT; c++) {
        #pragma unroll
        for (int kk = 0; kk < 3; kk++) {
            const int p = (kk + 1) * NTHREADS + tid;
            wr[c][kk] = *reinterpret_cast<const float4*>(&Wc[c * CSTRF + p * 4]);
        }
    }

    // ---- per-column persistent state in warp-0 registers ----
    const int j = j0 + lane;
    const bool active = (warp == 0) && (lane < CPT) && (j < NN);
    float v = 0.f, s = 0.f;
    float wi0 = 0.f, wi1 = 0.f, io = 0.f, o0 = 0.f, o1 = 0.f;
    if (active) {
        wi0 = W_in[j];
        wi1 = W_in[NN + j];
        io  = I_o[j];
        o0  = O[j];
        o1  = O[NN + j];
        __stcg(&g_state[0][j], make_float2(0.f, 0.f));   // t=0 reads parity-0 zeros
    }
    if (warp == 0 && lane == 0) red_release_add(&g_cnt[0], 1u);  // initial publish

    for (int t = 0; t < TT; t++) {
        const int rb = t & 1;
        const int wb = rb ^ 1;

        float x0 = 0.f, x1 = 0.f;
        if (warp == 0) {
            x0 = __ldg(&x_in[2 * t]);            // prefetch input before the wait
            x1 = __ldg(&x_in[2 * t + 1]);
            // wait until all CTAs published state readable at step t
            const unsigned* cp = &g_cnt[t];
            unsigned f = ld_relaxed_u32(cp);
            while ((int)(f - tgt0) < 0) {
                __nanosleep(16);
                f = ld_relaxed_u32(cp);
            }
            (void)ld_acquire_u32(cp);            // acquire: orders state loads below
        }
        __syncthreads();

        // ---- load state: 4 coalesced float4 (rows 2p, 2p+1 per float4) ----
        const float2* srow = g_state[rb];
        float4 st[4];
        #pragma unroll
        for (int k = 0; k < 4; k++) {
            const int p = k * NTHREADS + tid;
            st[k] = __ldcg(reinterpret_cast<const float4*>(&srow[2 * p]));
        }

        // ---- dot products: k=0 from SMEM (conflict-free LDS.128), k=1,2,3 from regs ----
        float acc[CPT];
        #pragma unroll
        for (int c = 0; c < CPT; c++) {
            float a = 0.f;
            {
                const float4 w = *reinterpret_cast<const float4*>(&Wc[c * CSTRF + tid * 4]);
                a = fmaf(st[0].x, w.x, a);
                a = fmaf(st[0].y, w.y, a);
                a = fmaf(st[0].z, w.z, a);
                a = fmaf(st[0].w, w.w, a);
            }
            #pragma unroll
            for (int kk = 0; kk < 3; kk++) {
                const float4 w = wr[c][kk];
                const float4 sv = st[kk + 1];
                a = fmaf(sv.x, w.x, a);
                a = fmaf(sv.y, w.y, a);
                a = fmaf(sv.z, w.z, a);
                a = fmaf(sv.w, w.w, a);
            }
            acc[c] = a;
        }

        // ---- intra-warp tree reduce, stash per-warp partials ----
        #pragma unroll
        for (int c = 0; c < CPT; c++) {
            float x = acc[c];
            x += __shfl_down_sync(0xffffffffu, x, 16);
            x += __shfl_down_sync(0xffffffffu, x, 8);
            x += __shfl_down_sync(0xffffffffu, x, 4);
            x += __shfl_down_sync(0xffffffffu, x, 2);
            x += __shfl_down_sync(0xffffffffu, x, 1);
            if (lane == 0) red[c * NWARPS + warp] = x;
        }
        __syncthreads();

        if (warp == 0) {
            float r0 = 0.f, r1 = 0.f;
            float s_new = 0.f, gd = 0.f, spk = 0.f, v_new = 0.f;
            if (active) {
                const float4 p0 = *reinterpret_cast<const float4*>(&red[lane * NWARPS]);
                const float4 p1 = *reinterpret_cast<const float4*>(&red[lane * NWARPS + 4]);
                const float sum = ((p0.x + p0.y) + (p0.z + p0.w)) +
                                  ((p1.x + p1.y) + (p1.z + p1.w));

                const float I_tot  = sum + x0 * wi0 + x1 * wi1 + io;
                const float dv     = (I_tot - v) / 10.0f;          // TAU_M
                const float v_next = v + dv;
                const float gating = fminf(fmaxf(v_next, -1.f), 1.f);
                const float dvc    = fminf(fmaxf(dv, -1.f), 1.f);
                gd                 = gating * dvc;
                s_new              = s + (gd - s) / 10.0f;         // TAU_S
                spk                = (v_next >=  1.f) ? 1.f : 0.f;
                const float sn     = (v_next <= -1.f) ? 1.f : 0.f;
                v_new              = (1.f + spk - sn) * v_next;    // matches reference exactly

                v = v_new; s = s_new;
                __stcg(&g_state[wb][j], make_float2(s_new, gd));
            }
            // publish progress FIRST (release orders the state stores above)
            if (lane == 0) red_release_add(&g_cnt[t + 1], 1u);

            // non-critical outputs after the release
            if (active) {
                out_spikes[(size_t)t * NN + j] = spk;
                out_vs[(size_t)t * NN + j]     = v_new;
                r0 = o0 * s_new;
                r1 = o1 * s_new;
            }
            #pragma unroll
            for (int o = 16; o; o >>= 1) {
                r0 += __shfl_down_sync(0xffffffffu, r0, o);
                r1 += __shfl_down_sync(0xffffffffu, r1, o);
            }
            if (lane == 0) {
                g_part[((size_t)t * G + b) * 2 + 0] = r0;
                g_part[((size_t)t * G + b) * 2 + 1] = r1;
            }
        }
    }

    // bump the epoch slot (one per CTA per replay)
    if (warp == 0 && lane == 0) red_release_add(&g_cnt[TT + 1], 1u);
}

// epilogue: one warp per timestep, coalesced float2 loads + shfl reduce
__global__ void readout_kernel(float* __restrict__ out_ro) {
    const int t    = blockIdx.x * (blockDim.x >> 5) + (threadIdx.x >> 5);
    const int lane = threadIdx.x & 31;
    if (t < TT) {
        const float2* p = reinterpret_cast<const float2*>(&g_part[(size_t)t * G * 2]);
        float a = 0.f, c = 0.f;
        for (int bb = lane; bb < G; bb += 32) {
            const float2 pv = p[bb];
            a += pv.x;
            c += pv.y;
        }
        #pragma unroll
        for (int o = 16; o; o >>= 1) {
            a += __shfl_down_sync(0xffffffffu, a, o);
            c += __shfl_down_sync(0xffffffffu, c, o);
        }
        if (lane == 0) {
            out_ro[2 * t]     = a;
            out_ro[2 * t + 1] = c;
        }
    }
}

extern "C" void kernel_launch(void* const* d_in, const int* in_sizes, int n_in,
                              void* d_out, int out_size) {
    const float* x_in   = (const float*)d_in[0];
    const float* W_syn  = (const float*)d_in[1];
    const float* W_fast = (const float*)d_in[2];
    const float* W_in   = (const float*)d_in[3];
    const float* I_o    = (const float*)d_in[4];
    const float* O      = (const float*)d_in[5];

    float* out        = (float*)d_out;
    float* out_spikes = out;                                // [T][N]
    float* out_ro     = out + (size_t)TT * NN;              // [T][2]
    float* out_vs     = out + (size_t)TT * NN + 2 * TT;     // [T][N]

    cudaFuncSetAttribute(nlif_kernel,
                         cudaFuncAttributeMaxDynamicSharedMemorySize, SMEM_BYTES);

    nlif_kernel<<<G, NTHREADS, SMEM_BYTES>>>(x_in, W_syn, W_fast, W_in, I_o, O,
                                             out_spikes, out_vs);
    // 8 warps per block, one warp per timestep
    readout_kernel<<<TT / 8, NTHREADS>>>(out_ro);
}